// round 14
// baseline (speedup 1.0000x reference)
#include <cuda_runtime.h>
#include <cuda_fp16.h>
#include <cstdint>

#define NV 512
#define NH 64
#define NB 4096

#define BM 256            // batch rows per block
#define BK 32             // K slice per stage
#define PIPE 4            // cp.async pipeline depth

// ---- main-kernel smem layout ----
#define A_PITCH   528                     // 256 halfs (512B) + 16B pad
#define A_BYTES   (BK * A_PITCH)          // 16896
#define B_ROW_B   80                      // 32 halfs + 8 pad
#define B_BYTES   (NH * B_ROW_B)          // 5120
#define STAGE_B   (A_BYTES + B_BYTES)     // 22016
#define SM_PARAMS (PIPE * STAGE_B)        // 88064
#define SM_IDX    (SM_PARAMS + 640)       // u16[512] = 1024 B
#define SMEM_MAIN (SM_IDX + 1024)         // 89728 -> 2 CTA/SM

// ---- static scratch (allowed) ----
__device__ __half   g_WC[(size_t)NV * NH * NV];  // [i][h][k'] compacted, zero-padded
__device__ __half   g_XT[(size_t)NV * NB];       // [v][b] fp16 transpose of X
__device__ uint16_t g_idx[NV * NV];              // [i][k'] active-parent list, 0-padded
__device__ int      g_cnt[NV];                   // active-parent count per net
__device__ uint16_t g_perm[NV];                  // nets sorted by cnt descending

__device__ __forceinline__ uint32_t smem_u32(const void* p) {
    uint32_t a;
    asm("{ .reg .u64 t; cvta.to.shared.u64 t, %1; cvt.u32.u64 %0, t; }" : "=r"(a) : "l"(p));
    return a;
}
__device__ __forceinline__ void cp16(uint32_t dst, const void* src) {
    asm volatile("cp.async.ca.shared.global [%0], [%1], 16;" :: "r"(dst), "l"(src));
}
__device__ __forceinline__ void cp_commit() {
    asm volatile("cp.async.commit_group;");
}
__device__ __forceinline__ void mma_f16(float c[4], const uint32_t a[4], const uint32_t b[2]) {
    asm volatile(
        "mma.sync.aligned.m16n8k16.row.col.f32.f16.f16.f32 "
        "{%0,%1,%2,%3}, {%4,%5,%6,%7}, {%8,%9}, {%0,%1,%2,%3};"
        : "+f"(c[0]), "+f"(c[1]), "+f"(c[2]), "+f"(c[3])
        : "r"(a[0]), "r"(a[1]), "r"(a[2]), "r"(a[3]), "r"(b[0]), "r"(b[1]));
}
__device__ __forceinline__ void mma_f16_k8(float c[4], uint32_t a0, uint32_t a1, uint32_t b0) {
    asm volatile(
        "mma.sync.aligned.m16n8k8.row.col.f32.f16.f16.f32 "
        "{%0,%1,%2,%3}, {%4,%5}, {%6}, {%0,%1,%2,%3};"
        : "+f"(c[0]), "+f"(c[1]), "+f"(c[2]), "+f"(c[3])
        : "r"(a0), "r"(a1), "r"(b0));
}
#define LDMX4T(d, a) \
    asm volatile("ldmatrix.sync.aligned.m8n8.x4.trans.shared.b16 {%0,%1,%2,%3}, [%4];" \
        : "=r"((d)[0]), "=r"((d)[1]), "=r"((d)[2]), "=r"((d)[3]) : "r"(a))

// ---------------- pre-pass 1: X -> XT[v][b] fp16 ----------------
__global__ __launch_bounds__(256) void xt_kernel(const float* __restrict__ X) {
    __shared__ float tile[64][65];
    const int tx = threadIdx.x & 63, ty = threadIdx.x >> 6;   // 64 x 4
    const int b0 = blockIdx.x * 64, v0 = blockIdx.y * 64;
    #pragma unroll
    for (int j = 0; j < 16; j++) {
        int row = ty + j * 4;
        tile[row][tx] = X[(size_t)(b0 + row) * NV + v0 + tx];
    }
    __syncthreads();
    #pragma unroll
    for (int j = 0; j < 16; j++) {
        int v = ty + j * 4;
        g_XT[(size_t)(v0 + v) * NB + b0 + tx] = __float2half_rn(tile[tx][v]);
    }
}

// ---------------- pre-pass 2: per-net compaction + fused adj output ----------------
#define CWS_MASK (NV * 66 * 2)            // tile[512][66] half
#define CWS_SIDX (CWS_MASK + 64)          // u16[512]
#define CWS_CNT  (CWS_SIDX + 1024)
#define CW_SMEM  (CWS_CNT + 16)
__global__ __launch_bounds__(256) void compact_kernel(const float* __restrict__ W1,
                                                      const float* __restrict__ logits,
                                                      float* __restrict__ out) {
    extern __shared__ char cs[];
    __half*   tile  = reinterpret_cast<__half*>(cs);
    uint32_t* masks = reinterpret_cast<uint32_t*>(cs + CWS_MASK);
    uint16_t* sidx  = reinterpret_cast<uint16_t*>(cs + CWS_SIDX);
    int*      scnt  = reinterpret_cast<int*>(cs + CWS_CNT);
    const int i = blockIdx.x, tid = threadIdx.x;
    const int warp = tid >> 5, lane = tid & 31;

    bool bits[2];
    #pragma unroll
    for (int r = 0; r < 2; r++) {
        int v = tid + r * 256;
        bits[r] = (logits[(size_t)v * NV + i] > 0.0f) && (v != i);
        uint32_t m = __ballot_sync(0xFFFFFFFFu, bits[r]);
        if (lane == 0) masks[warp + r * 8] = m;
        out[(size_t)NB * NV + (size_t)v * NV + i] = bits[r] ? 1.0f : 0.0f;
    }
    __syncthreads();
    #pragma unroll
    for (int r = 0; r < 2; r++) {
        int v = tid + r * 256;
        int wi = warp + r * 8;
        int base = 0;
        for (int j = 0; j < wi; j++) base += __popc(masks[j]);
        int pos = base + __popc(masks[wi] & ((1u << lane) - 1u));
        if (bits[r]) sidx[pos] = (uint16_t)v;
    }
    if (tid == 0) {
        int c = 0;
        for (int j = 0; j < 16; j++) c += __popc(masks[j]);
        scnt[0] = c;
        g_cnt[i] = c;
    }
    __syncthreads();
    const int cnt = scnt[0];
    for (int k = tid; k < NV; k += 256)
        g_idx[i * NV + k] = (k < cnt) ? sidx[k] : (uint16_t)0;

    const float4* w = reinterpret_cast<const float4*>(W1 + (size_t)i * NV * NH);
    #pragma unroll
    for (int l = 0; l < 32; l++) {
        int e = tid + l * 256;            // 8192 float4 over [v][h4]
        int v = e >> 4, h4 = e & 15;
        float4 x = w[e];
        __half* dst = &tile[v * 66 + 4 * h4];
        dst[0] = __float2half_rn(x.x);
        dst[1] = __float2half_rn(x.y);
        dst[2] = __float2half_rn(x.z);
        dst[3] = __float2half_rn(x.w);
    }
    __syncthreads();

    const int lim = (cnt + 31) & ~31;
    #pragma unroll
    for (int l = 0; l < 64; l++) {
        int f = tid + l * 256;
        int h = f >> 8, kp = f & 255;
        int k0 = 2 * kp, k1 = k0 + 1;
        if (k0 < lim) {
            __half2 o;
            o.x = (k0 < cnt) ? tile[(int)sidx[k0] * 66 + h] : __half(0.0f);
            o.y = (k1 < cnt) ? tile[(int)sidx[k1] * 66 + h] : __half(0.0f);
            reinterpret_cast<__half2*>(g_WC + (((size_t)i * NH + h) << 9))[kp] = o;
        }
    }
}

// ---------------- pre-pass 3: sort nets by cnt (descending) ----------------
__global__ __launch_bounds__(512) void rank_kernel() {
    __shared__ int cs[NV];
    const int i = threadIdx.x;
    cs[i] = g_cnt[i];
    __syncthreads();
    const int c = cs[i];
    int r = 0;
    #pragma unroll 8
    for (int j = 0; j < NV; j++) {
        int cj = cs[j];
        r += (cj > c) || (cj == c && j < i);
    }
    g_perm[r] = (uint16_t)i;
}

// ---------------- main GEMM + fused epilogue (one net per block) ----------------
__global__ __launch_bounds__(256, 2)
void dag_f16_kernel(const float* __restrict__ b1,
                    const float* __restrict__ W2,
                    const float* __restrict__ b2,
                    float* __restrict__ out)
{
    extern __shared__ char smem[];
    const uint32_t sb = smem_u32(smem);
    const int tid  = threadIdx.x;
    const int warp = tid >> 5;           // 0..7 : 32-row m-slice
    const int lane = tid & 31;
    const int g    = lane >> 2;
    const int t    = lane & 3;

    const int i     = g_perm[blockIdx.y];
    const int bbase = blockIdx.x * BM;

    float* b1s = reinterpret_cast<float*>(smem + SM_PARAMS);          // [64]
    float* w2s = reinterpret_cast<float*>(smem + SM_PARAMS + 256);    // [64]
    float* b2s = reinterpret_cast<float*>(smem + SM_PARAMS + 512);    // [1]
    uint16_t* idxs = reinterpret_cast<uint16_t*>(smem + SM_IDX);      // [512]
    if (tid < 64) {
        b1s[tid] = b1[(size_t)i * NH + tid];
        w2s[tid] = W2[(size_t)i * NH + tid];
        if (tid == 0) b2s[0] = b2[i];
    }
    reinterpret_cast<uint32_t*>(idxs)[tid] =
        reinterpret_cast<const uint32_t*>(g_idx + (size_t)i * NV)[tid];
    const int cnt = g_cnt[i];
    const int ns  = (cnt + 31) >> 5;
    const int rem = cnt - ((ns - 1) << 5);   // (0, 32]
    __syncthreads();

    float acc[2][8][4];
    #pragma unroll
    for (int mt = 0; mt < 2; mt++)
        #pragma unroll
        for (int nt = 0; nt < 8; nt++)
            #pragma unroll
            for (int q = 0; q < 4; q++) acc[mt][nt][q] = 0.0f;

    auto load_stage = [&](int s) {
        const int buf = s & 3;
        const uint32_t aB = sb + buf * STAGE_B;
        const uint32_t bB = aB + A_BYTES;
        #pragma unroll
        for (int l = 0; l < 4; l++) {         // A: 1024 chunks, gathered rows of XT
            int c = tid + l * 256;
            int krow = c >> 5, mc = c & 31;
            uint32_t xrow = idxs[s * BK + krow];
            cp16(aB + krow * A_PITCH + mc * 16,
                 g_XT + (size_t)xrow * NB + bbase + mc * 8);
        }
        {                                     // B: 256 chunks from compact WC
            int n = tid >> 2, q = tid & 3;    // n = h (0..63)
            cp16(bB + n * B_ROW_B + q * 16,
                 g_WC + (((size_t)i * NH + n) << 9) + s * BK + q * 8);
        }
        cp_commit();
    };

    #pragma unroll
    for (int sp = 0; sp < 3; sp++) {
        if (sp < ns) load_stage(sp); else cp_commit();
    }

    // A-side ldmatrix.x4.trans lane offset (constant across stages)
    const int lr   = lane & 7;
    const int sel  = lane >> 3;
    const int kofs = (sel & 2) ? 8 : 0;
    const int mofs = (sel & 1) ? 8 : 0;
    const uint32_t a_lane_off =
        (uint32_t)((kofs + lr) * A_PITCH + (warp * 32 + mofs) * 2);

    // one k16 halfstage of MMAs
    auto do_kk = [&](int kk, uint32_t aBl, const char* bBc) {
        uint32_t afr[2][4];
        #pragma unroll
        for (int mt = 0; mt < 2; mt++)
            LDMX4T(afr[mt], aBl + kk * (16 * A_PITCH) + mt * 32);
        uint32_t bfr[8][2];
        #pragma unroll
        for (int nt = 0; nt < 8; nt++) {
            int n = nt * 8 + g;
            const char* p = bBc + (n * 20 + kk * 8 + t) * 4;
            bfr[nt][0] = *reinterpret_cast<const uint32_t*>(p);
            bfr[nt][1] = *reinterpret_cast<const uint32_t*>(p + 16);
        }
        #pragma unroll
        for (int mt = 0; mt < 2; mt++)
            #pragma unroll
            for (int nt = 0; nt < 8; nt++)
                mma_f16(acc[mt][nt], afr[mt], bfr[nt]);
    };
    // k8 variant: uses only the low-k halves of the fragments
    auto do_kk8 = [&](int kk, uint32_t aBl, const char* bBc) {
        uint32_t afr[2][4];
        #pragma unroll
        for (int mt = 0; mt < 2; mt++)
            LDMX4T(afr[mt], aBl + kk * (16 * A_PITCH) + mt * 32);
        uint32_t bfr[8];
        #pragma unroll
        for (int nt = 0; nt < 8; nt++) {
            int n = nt * 8 + g;
            const char* p = bBc + (n * 20 + kk * 8 + t) * 4;
            bfr[nt] = *reinterpret_cast<const uint32_t*>(p);
        }
        #pragma unroll
        for (int mt = 0; mt < 2; mt++)
            #pragma unroll
            for (int nt = 0; nt < 8; nt++)
                mma_f16_k8(acc[mt][nt], afr[mt][0], afr[mt][1], bfr[nt]);
    };

    // full stages (branch-free hot loop)
    for (int s = 0; s < ns - 1; s++) {
        asm volatile("cp.async.wait_group 2;" ::: "memory");
        __syncthreads();
        if (s + 3 < ns) load_stage(s + 3); else cp_commit();

        const int buf = s & 3;
        const uint32_t aBl = sb + buf * STAGE_B + a_lane_off;
        const char* bBc = smem + buf * STAGE_B + A_BYTES;
        do_kk(0, aBl, bBc);
        do_kk(1, aBl, bBc);
    }

    // tail stage s = ns-1, k8-granular
    if (ns >= 1) {
        asm volatile("cp.async.wait_group 2;" ::: "memory");
        __syncthreads();

        const int buf = (ns - 1) & 3;
        const uint32_t aBl = sb + buf * STAGE_B + a_lane_off;
        const char* bBc = smem + buf * STAGE_B + A_BYTES;
        if (rem <= 8)        do_kk8(0, aBl, bBc);
        else                 do_kk (0, aBl, bBc);
        if (rem > 16) {
            if (rem <= 24)   do_kk8(1, aBl, bBc);
            else             do_kk (1, aBl, bBc);
        }
    }

    // epilogue: recon[row][i] = sum_h relu(acc + b1) * w2 + b2
    #pragma unroll
    for (int mt = 0; mt < 2; mt++) {
        #pragma unroll
        for (int half = 0; half < 2; half++) {
            float sum = 0.0f;
            #pragma unroll
            for (int nt = 0; nt < 8; nt++) {
                int col = nt * 8 + 2 * t;
                float v0 = acc[mt][nt][half * 2 + 0];
                float v1 = acc[mt][nt][half * 2 + 1];
                sum += fmaxf(v0 + b1s[col],     0.0f) * w2s[col];
                sum += fmaxf(v1 + b1s[col + 1], 0.0f) * w2s[col + 1];
            }
            sum += __shfl_xor_sync(0xFFFFFFFFu, sum, 1);
            sum += __shfl_xor_sync(0xFFFFFFFFu, sum, 2);
            if (t == 0) {
                int row = bbase + warp * 32 + mt * 16 + half * 8 + g;
                out[(size_t)row * NV + i] = sum + b2s[0];
            }
        }
    }
}

extern "C" void kernel_launch(void* const* d_in, const int* in_sizes, int n_in,
                              void* d_out, int out_size)
{
    const float* X      = (const float*)d_in[0];
    const float* logits = (const float*)d_in[1];
    const float* W1     = (const float*)d_in[2];
    const float* b1     = (const float*)d_in[3];
    const float* W2     = (const float*)d_in[4];
    const float* b2     = (const float*)d_in[5];
    float* out          = (float*)d_out;

    static bool init_done = false;
    static cudaStream_t s_side;
    static cudaEvent_t e_fork, e_join;
    if (!init_done) {
        cudaFuncSetAttribute(compact_kernel, cudaFuncAttributeMaxDynamicSharedMemorySize, CW_SMEM);
        cudaFuncSetAttribute(dag_f16_kernel, cudaFuncAttributeMaxDynamicSharedMemorySize, SMEM_MAIN);
        cudaStreamCreateWithFlags(&s_side, cudaStreamNonBlocking);
        cudaEventCreateWithFlags(&e_fork, cudaEventDisableTiming);
        cudaEventCreateWithFlags(&e_join, cudaEventDisableTiming);
        init_done = true;
    }

    // fork: xt runs concurrently with compact+rank
    cudaEventRecord(e_fork, 0);
    cudaStreamWaitEvent(s_side, e_fork, 0);

    dim3 xtg(NB / 64, NV / 64);
    xt_kernel<<<xtg, 256, 0, s_side>>>(X);

    compact_kernel<<<NV, 256, CW_SMEM>>>(W1, logits, out);
    rank_kernel<<<1, NV>>>();

    // join
    cudaEventRecord(e_join, s_side);
    cudaStreamWaitEvent(0, e_join, 0);

    dim3 grid(NB / BM, NV);               // (16, 512)
    dag_f16_kernel<<<grid, 256, SMEM_MAIN>>>(b1, W2, b2, out);
}

// round 15
// speedup vs baseline: 1.0499x; 1.0499x over previous
#include <cuda_runtime.h>
#include <cuda_fp16.h>
#include <cstdint>

#define NV 512
#define NH 64
#define NB 4096

#define BM 256            // batch rows per block
#define BK 32             // K slice per stage
#define PIPE 4            // cp.async pipeline depth

// ---- main-kernel smem layout ----
#define A_PITCH   528                     // 256 halfs (512B) + 16B pad
#define A_BYTES   (BK * A_PITCH)          // 16896
#define B_ROW_B   80                      // 32 halfs + 8 pad
#define B_BYTES   (NH * B_ROW_B)          // 5120
#define STAGE_B   (A_BYTES + B_BYTES)     // 22016
#define SM_PARAMS (PIPE * STAGE_B)        // 88064
#define SM_IDX    (SM_PARAMS + 640)       // u16[512] = 1024 B
#define SMEM_MAIN (SM_IDX + 1024)         // 89728 -> 2 CTA/SM

// ---- static scratch (allowed) ----
__device__ __half   g_WC[(size_t)NV * NH * NV];  // [i][h][k'] compacted, zero-padded
__device__ __half   g_XT[(size_t)NV * NB];       // [v][b] fp16 transpose of X
__device__ uint16_t g_idx[NV * NV];              // [i][k'] active-parent list, 0-padded
__device__ int      g_cnt[NV];                   // active-parent count per net
__device__ uint16_t g_perm[NV];                  // nets sorted by cnt descending

__device__ __forceinline__ uint32_t smem_u32(const void* p) {
    uint32_t a;
    asm("{ .reg .u64 t; cvta.to.shared.u64 t, %1; cvt.u32.u64 %0, t; }" : "=r"(a) : "l"(p));
    return a;
}
__device__ __forceinline__ void cp16(uint32_t dst, const void* src) {
    asm volatile("cp.async.ca.shared.global [%0], [%1], 16;" :: "r"(dst), "l"(src));
}
__device__ __forceinline__ void cp_commit() {
    asm volatile("cp.async.commit_group;");
}
__device__ __forceinline__ void mma_f16(float c[4], const uint32_t a[4], const uint32_t b[2]) {
    asm volatile(
        "mma.sync.aligned.m16n8k16.row.col.f32.f16.f16.f32 "
        "{%0,%1,%2,%3}, {%4,%5,%6,%7}, {%8,%9}, {%0,%1,%2,%3};"
        : "+f"(c[0]), "+f"(c[1]), "+f"(c[2]), "+f"(c[3])
        : "r"(a[0]), "r"(a[1]), "r"(a[2]), "r"(a[3]), "r"(b[0]), "r"(b[1]));
}
#define LDMX4T(d, a) \
    asm volatile("ldmatrix.sync.aligned.m8n8.x4.trans.shared.b16 {%0,%1,%2,%3}, [%4];" \
        : "=r"((d)[0]), "=r"((d)[1]), "=r"((d)[2]), "=r"((d)[3]) : "r"(a))

// ---------------- pre-pass 1: X -> XT[v][b] fp16 ----------------
__global__ __launch_bounds__(256) void xt_kernel(const float* __restrict__ X) {
    __shared__ float tile[64][65];
    const int tx = threadIdx.x & 63, ty = threadIdx.x >> 6;   // 64 x 4
    const int b0 = blockIdx.x * 64, v0 = blockIdx.y * 64;
    #pragma unroll
    for (int j = 0; j < 16; j++) {
        int row = ty + j * 4;
        tile[row][tx] = X[(size_t)(b0 + row) * NV + v0 + tx];
    }
    __syncthreads();
    #pragma unroll
    for (int j = 0; j < 16; j++) {
        int v = ty + j * 4;
        g_XT[(size_t)(v0 + v) * NB + b0 + tx] = __float2half_rn(tile[tx][v]);
    }
}

// ---------------- pre-pass 2: per-net compaction (active rows only) ----------------
#define CWS_MASK (NV * 66 * 2)            // tile[kp][66] half (up to 512 rows)
#define CWS_SIDX (CWS_MASK + 64)          // u16[512]
#define CWS_CNT  (CWS_SIDX + 1024)
#define CW_SMEM  (CWS_CNT + 16)
__global__ __launch_bounds__(256) void compact_kernel(const float* __restrict__ W1,
                                                      const float* __restrict__ logits) {
    extern __shared__ char cs[];
    __half*   tile  = reinterpret_cast<__half*>(cs);
    uint32_t* masks = reinterpret_cast<uint32_t*>(cs + CWS_MASK);
    uint16_t* sidx  = reinterpret_cast<uint16_t*>(cs + CWS_SIDX);
    int*      scnt  = reinterpret_cast<int*>(cs + CWS_CNT);
    const int i = blockIdx.x, tid = threadIdx.x;
    const int warp = tid >> 5, lane = tid & 31;

    bool bits[2];
    #pragma unroll
    for (int r = 0; r < 2; r++) {
        int v = tid + r * 256;
        bits[r] = (logits[(size_t)v * NV + i] > 0.0f) && (v != i);
        uint32_t m = __ballot_sync(0xFFFFFFFFu, bits[r]);
        if (lane == 0) masks[warp + r * 8] = m;
    }
    __syncthreads();
    #pragma unroll
    for (int r = 0; r < 2; r++) {
        int v = tid + r * 256;
        int wi = warp + r * 8;
        int base = 0;
        for (int j = 0; j < wi; j++) base += __popc(masks[j]);
        int pos = base + __popc(masks[wi] & ((1u << lane) - 1u));
        if (bits[r]) sidx[pos] = (uint16_t)v;
    }
    if (tid == 0) {
        int c = 0;
        for (int j = 0; j < 16; j++) c += __popc(masks[j]);
        scnt[0] = c;
        g_cnt[i] = c;
    }
    __syncthreads();
    const int cnt = scnt[0];
    for (int k = tid; k < NV; k += 256)
        g_idx[i * NV + k] = (k < cnt) ? sidx[k] : (uint16_t)0;

    // load ONLY active rows, directly compacted: tile[kp][h] = W1[i][sidx[kp]][h]
    const float4* w = reinterpret_cast<const float4*>(W1 + (size_t)i * NV * NH);
    for (int e = tid; e < cnt * 16; e += 256) {
        int kp = e >> 4, h4 = e & 15;
        int v = sidx[kp];
        float4 x = w[v * 16 + h4];
        __half* dst = &tile[kp * 66 + 4 * h4];
        dst[0] = __float2half_rn(x.x);
        dst[1] = __float2half_rn(x.y);
        dst[2] = __float2half_rn(x.z);
        dst[3] = __float2half_rn(x.w);
    }
    __syncthreads();

    // transpose-write to g_WC[i][h][k'], only up to the padded stage boundary
    const int lim = (cnt + 31) & ~31;
    #pragma unroll
    for (int l = 0; l < 64; l++) {
        int f = tid + l * 256;
        int h = f >> 8, kp = f & 255;
        int k0 = 2 * kp, k1 = k0 + 1;
        if (k0 < lim) {
            __half2 o;
            o.x = (k0 < cnt) ? tile[k0 * 66 + h] : __half(0.0f);
            o.y = (k1 < cnt) ? tile[k1 * 66 + h] : __half(0.0f);
            reinterpret_cast<__half2*>(g_WC + (((size_t)i * NH + h) << 9))[kp] = o;
        }
    }
}

// ---------------- pre-pass 3: sort nets by cnt (descending) ----------------
__global__ __launch_bounds__(512) void rank_kernel() {
    __shared__ int cs[NV];
    const int i = threadIdx.x;
    cs[i] = g_cnt[i];
    __syncthreads();
    const int c = cs[i];
    int r = 0;
    #pragma unroll 8
    for (int j = 0; j < NV; j++) {
        int cj = cs[j];
        r += (cj > c) || (cj == c && j < i);
    }
    g_perm[r] = (uint16_t)i;
}

// ---------------- main GEMM + fused epilogue (R13-proven body) ----------------
__global__ __launch_bounds__(256, 2)
void dag_f16_kernel(const float* __restrict__ b1,
                    const float* __restrict__ W2,
                    const float* __restrict__ b2,
                    float* __restrict__ out)
{
    extern __shared__ char smem[];
    const uint32_t sb = smem_u32(smem);
    const int tid  = threadIdx.x;
    const int warp = tid >> 5;           // 0..7 : 32-row m-slice
    const int lane = tid & 31;
    const int g    = lane >> 2;
    const int t    = lane & 3;

    const int i     = g_perm[blockIdx.y];
    const int bbase = blockIdx.x * BM;

    float* b1s = reinterpret_cast<float*>(smem + SM_PARAMS);          // [64]
    float* w2s = reinterpret_cast<float*>(smem + SM_PARAMS + 256);    // [64]
    float* b2s = reinterpret_cast<float*>(smem + SM_PARAMS + 512);    // [1]
    uint16_t* idxs = reinterpret_cast<uint16_t*>(smem + SM_IDX);      // [512]
    if (tid < 64) {
        b1s[tid] = b1[(size_t)i * NH + tid];
        w2s[tid] = W2[(size_t)i * NH + tid];
        if (tid == 0) b2s[0] = b2[i];
    }
    reinterpret_cast<uint32_t*>(idxs)[tid] =
        reinterpret_cast<const uint32_t*>(g_idx + (size_t)i * NV)[tid];
    const int cnt = g_cnt[i];
    const int ns  = (cnt + 31) >> 5;
    // last stage covers only the low half (k-rows <= 16)? then skip its kk=1
    const int lastkk = (cnt - ((ns - 1) << 5) <= 16) ? 1 : 2;
    __syncthreads();

    float acc[2][8][4];
    #pragma unroll
    for (int mt = 0; mt < 2; mt++)
        #pragma unroll
        for (int nt = 0; nt < 8; nt++)
            #pragma unroll
            for (int q = 0; q < 4; q++) acc[mt][nt][q] = 0.0f;

    auto load_stage = [&](int s) {
        const int buf = s & 3;
        const uint32_t aB = sb + buf * STAGE_B;
        const uint32_t bB = aB + A_BYTES;
        #pragma unroll
        for (int l = 0; l < 4; l++) {         // A: 1024 chunks, gathered rows of XT
            int c = tid + l * 256;
            int krow = c >> 5, mc = c & 31;
            uint32_t xrow = idxs[s * BK + krow];
            cp16(aB + krow * A_PITCH + mc * 16,
                 g_XT + (size_t)xrow * NB + bbase + mc * 8);
        }
        {                                     // B: 256 chunks from compact WC
            int n = tid >> 2, q = tid & 3;    // n = h (0..63)
            cp16(bB + n * B_ROW_B + q * 16,
                 g_WC + (((size_t)i * NH + n) << 9) + s * BK + q * 8);
        }
        cp_commit();
    };

    #pragma unroll
    for (int sp = 0; sp < 3; sp++) {
        if (sp < ns) load_stage(sp); else cp_commit();
    }

    // A-side ldmatrix.x4.trans lane offset (constant across stages)
    const int lr   = lane & 7;
    const int sel  = lane >> 3;
    const int kofs = (sel & 2) ? 8 : 0;
    const int mofs = (sel & 1) ? 8 : 0;
    const uint32_t a_lane_off =
        (uint32_t)((kofs + lr) * A_PITCH + (warp * 32 + mofs) * 2);

    // one k8-halfstage of MMAs (kk constant at each inlined call site)
    auto do_kk = [&](int kk, uint32_t aBl, const char* bBc) {
        uint32_t afr[2][4];
        #pragma unroll
        for (int mt = 0; mt < 2; mt++)
            LDMX4T(afr[mt], aBl + kk * (16 * A_PITCH) + mt * 32);
        uint32_t bfr[8][2];
        #pragma unroll
        for (int nt = 0; nt < 8; nt++) {
            int n = nt * 8 + g;
            const char* p = bBc + (n * 20 + kk * 8 + t) * 4;
            bfr[nt][0] = *reinterpret_cast<const uint32_t*>(p);
            bfr[nt][1] = *reinterpret_cast<const uint32_t*>(p + 16);
        }
        #pragma unroll
        for (int mt = 0; mt < 2; mt++)
            #pragma unroll
            for (int nt = 0; nt < 8; nt++)
                mma_f16(acc[mt][nt], afr[mt], bfr[nt]);
    };

    for (int s = 0; s < ns; s++) {
        asm volatile("cp.async.wait_group 2;" ::: "memory");
        __syncthreads();
        if (s + 3 < ns) load_stage(s + 3); else cp_commit();

        const int buf = s & 3;
        const uint32_t aBl = sb + buf * STAGE_B + a_lane_off;
        const char* bBc = smem + buf * STAGE_B + A_BYTES;

        do_kk(0, aBl, bBc);
        if (s + 1 < ns || lastkk == 2)
            do_kk(1, aBl, bBc);
    }

    // epilogue: recon[row][i] = sum_h relu(acc + b1) * w2 + b2
    #pragma unroll
    for (int mt = 0; mt < 2; mt++) {
        #pragma unroll
        for (int half = 0; half < 2; half++) {
            float sum = 0.0f;
            #pragma unroll
            for (int nt = 0; nt < 8; nt++) {
                int col = nt * 8 + 2 * t;
                float v0 = acc[mt][nt][half * 2 + 0];
                float v1 = acc[mt][nt][half * 2 + 1];
                sum += fmaxf(v0 + b1s[col],     0.0f) * w2s[col];
                sum += fmaxf(v1 + b1s[col + 1], 0.0f) * w2s[col + 1];
            }
            sum += __shfl_xor_sync(0xFFFFFFFFu, sum, 1);
            sum += __shfl_xor_sync(0xFFFFFFFFu, sum, 2);
            if (t == 0) {
                int row = bbase + warp * 32 + mt * 16 + half * 8 + g;
                out[(size_t)row * NV + i] = sum + b2s[0];
            }
        }
    }
}

// adjacency block of output (coalesced writes)
__global__ void adj_kernel(const float* __restrict__ logits, float* __restrict__ out) {
    int idx = blockIdx.x * blockDim.x + threadIdx.x;
    if (idx < NV * NV) {
        int v = idx / NV, u = idx % NV;
        out[(size_t)NB * NV + idx] = (logits[idx] > 0.0f && v != u) ? 1.0f : 0.0f;
    }
}

extern "C" void kernel_launch(void* const* d_in, const int* in_sizes, int n_in,
                              void* d_out, int out_size)
{
    const float* X      = (const float*)d_in[0];
    const float* logits = (const float*)d_in[1];
    const float* W1     = (const float*)d_in[2];
    const float* b1     = (const float*)d_in[3];
    const float* W2     = (const float*)d_in[4];
    const float* b2     = (const float*)d_in[5];
    float* out          = (float*)d_out;

    static bool attr_done = false;
    if (!attr_done) {
        cudaFuncSetAttribute(compact_kernel, cudaFuncAttributeMaxDynamicSharedMemorySize, CW_SMEM);
        cudaFuncSetAttribute(dag_f16_kernel, cudaFuncAttributeMaxDynamicSharedMemorySize, SMEM_MAIN);
        attr_done = true;
    }

    dim3 xtg(NB / 64, NV / 64);
    xt_kernel<<<xtg, 256>>>(X);
    compact_kernel<<<NV, 256, CW_SMEM>>>(W1, logits);
    rank_kernel<<<1, NV>>>();

    dim3 grid(NB / BM, NV);               // (16, 512)
    dag_f16_kernel<<<grid, 256, SMEM_MAIN>>>(b1, W2, b2, out);

    adj_kernel<<<(NV * NV + 255) / 256, 256>>>(logits, out);
}

// round 16
// speedup vs baseline: 1.0683x; 1.0175x over previous
#include <cuda_runtime.h>
#include <cuda_fp16.h>
#include <cstdint>

#define NV 512
#define NH 64
#define NB 4096

#define BM 256            // batch rows per block
#define BK 32             // K slice per stage
#define PIPE 4            // cp.async pipeline depth

// ---- main-kernel smem layout ----
#define A_PITCH   528                     // 256 halfs (512B) + 16B pad
#define A_BYTES   (BK * A_PITCH)          // 16896
#define B_ROW_B   80                      // 32 halfs + 8 pad
#define B_BYTES   (NH * B_ROW_B)          // 5120
#define STAGE_B   (A_BYTES + B_BYTES)     // 22016
#define SM_PARAMS (PIPE * STAGE_B)        // 88064
#define SM_IDX    (SM_PARAMS + 640)       // u16[512] = 1024 B
#define SMEM_MAIN (SM_IDX + 1024)         // 89728 -> 2 CTA/SM

// ---- static scratch (allowed) ----
__device__ __half   g_WC[(size_t)NV * NH * NV];  // [i][h][k'] compacted, zero-padded
__device__ __half   g_XT[(size_t)NV * NB];       // [v][b] fp16 transpose of X
__device__ uint16_t g_idx[NV * NV];              // [i][k'] active-parent list, 0-padded
__device__ int      g_cnt[NV];                   // active-parent count per net
__device__ uint16_t g_perm[NV];                  // nets sorted by cnt descending

__device__ __forceinline__ uint32_t smem_u32(const void* p) {
    uint32_t a;
    asm("{ .reg .u64 t; cvta.to.shared.u64 t, %1; cvt.u32.u64 %0, t; }" : "=r"(a) : "l"(p));
    return a;
}
__device__ __forceinline__ void cp16(uint32_t dst, const void* src) {
    asm volatile("cp.async.ca.shared.global [%0], [%1], 16;" :: "r"(dst), "l"(src));
}
__device__ __forceinline__ void cp_commit() {
    asm volatile("cp.async.commit_group;");
}
__device__ __forceinline__ void mma_f16(float c[4], const uint32_t a[4], const uint32_t b[2]) {
    asm volatile(
        "mma.sync.aligned.m16n8k16.row.col.f32.f16.f16.f32 "
        "{%0,%1,%2,%3}, {%4,%5,%6,%7}, {%8,%9}, {%0,%1,%2,%3};"
        : "+f"(c[0]), "+f"(c[1]), "+f"(c[2]), "+f"(c[3])
        : "r"(a[0]), "r"(a[1]), "r"(a[2]), "r"(a[3]), "r"(b[0]), "r"(b[1]));
}
#define LDMX4T(d, a) \
    asm volatile("ldmatrix.sync.aligned.m8n8.x4.trans.shared.b16 {%0,%1,%2,%3}, [%4];" \
        : "=r"((d)[0]), "=r"((d)[1]), "=r"((d)[2]), "=r"((d)[3]) : "r"(a))

// ---------------- pre-pass 1: X -> XT[v][b] fp16, + fused adj output ----------------
__global__ __launch_bounds__(256) void xt_kernel(const float* __restrict__ X,
                                                 const float* __restrict__ logits,
                                                 float* __restrict__ out) {
    __shared__ float tile[64][65];
    const int tx = threadIdx.x & 63, ty = threadIdx.x >> 6;   // 64 x 4
    const int b0 = blockIdx.x * 64, v0 = blockIdx.y * 64;
    #pragma unroll
    for (int j = 0; j < 16; j++) {
        int row = ty + j * 4;
        tile[row][tx] = X[(size_t)(b0 + row) * NV + v0 + tx];
    }
    __syncthreads();
    #pragma unroll
    for (int j = 0; j < 16; j++) {
        int v = ty + j * 4;
        g_XT[(size_t)(v0 + v) * NB + b0 + tx] = __float2half_rn(tile[tx][v]);
    }
    // fused adjacency block: 512 blocks x 512 elems, coalesced
    const int bid = blockIdx.y * 64 + blockIdx.x;             // 0..511
    #pragma unroll
    for (int l = 0; l < 2; l++) {
        int idx = bid * 512 + l * 256 + threadIdx.x;
        int v = idx >> 9, u = idx & 511;
        out[(size_t)NB * NV + idx] =
            (logits[idx] > 0.0f && v != u) ? 1.0f : 0.0f;
    }
}

// ---------------- pre-pass 2: per-net compaction (512 threads, active rows only) ----------------
#define CWS_MASK (NV * 66 * 2)            // tile[kp][66] half (up to 512 rows)
#define CWS_SIDX (CWS_MASK + 64)          // u16[512] (masks = 16 u32 = 64B)
#define CWS_CNT  (CWS_SIDX + 1024)
#define CW_SMEM  (CWS_CNT + 16)
__global__ __launch_bounds__(512) void compact_kernel(const float* __restrict__ W1,
                                                      const float* __restrict__ logits) {
    extern __shared__ char cs[];
    __half*   tile  = reinterpret_cast<__half*>(cs);
    uint32_t* masks = reinterpret_cast<uint32_t*>(cs + CWS_MASK);
    uint16_t* sidx  = reinterpret_cast<uint16_t*>(cs + CWS_SIDX);
    int*      scnt  = reinterpret_cast<int*>(cs + CWS_CNT);
    const int i = blockIdx.x, tid = threadIdx.x;
    const int warp = tid >> 5, lane = tid & 31;

    const int v = tid;                                    // 0..511
    const bool bit = (logits[(size_t)v * NV + i] > 0.0f) && (v != i);
    {
        uint32_t m = __ballot_sync(0xFFFFFFFFu, bit);
        if (lane == 0) masks[warp] = m;
    }
    __syncthreads();
    {
        int base = 0;
        #pragma unroll
        for (int j = 0; j < 16; j++)
            base += (j < warp) ? __popc(masks[j]) : 0;
        int pos = base + __popc(masks[warp] & ((1u << lane) - 1u));
        if (bit) sidx[pos] = (uint16_t)v;
    }
    if (tid == 0) {
        int c = 0;
        #pragma unroll
        for (int j = 0; j < 16; j++) c += __popc(masks[j]);
        scnt[0] = c;
        g_cnt[i] = c;
    }
    __syncthreads();
    const int cnt = scnt[0];
    g_idx[i * NV + tid] = (tid < cnt) ? sidx[tid] : (uint16_t)0;

    // load ONLY active rows, directly compacted: tile[kp][h] = W1[i][sidx[kp]][h]
    const float4* w = reinterpret_cast<const float4*>(W1 + (size_t)i * NV * NH);
    for (int e = tid; e < cnt * 16; e += 512) {
        int kp = e >> 4, h4 = e & 15;
        int vr = sidx[kp];
        float4 x = w[vr * 16 + h4];
        __half* dst = &tile[kp * 66 + 4 * h4];
        dst[0] = __float2half_rn(x.x);
        dst[1] = __float2half_rn(x.y);
        dst[2] = __float2half_rn(x.z);
        dst[3] = __float2half_rn(x.w);
    }
    __syncthreads();

    // transpose-write to g_WC[i][h][k'], only up to the padded stage boundary
    const int lim = (cnt + 31) & ~31;
    #pragma unroll
    for (int l = 0; l < 32; l++) {
        int f = tid + l * 512;            // 16384 over h(64) x kp(256)
        int h = f >> 8, kp = f & 255;
        int k0 = 2 * kp, k1 = k0 + 1;
        if (k0 < lim) {
            __half2 o;
            o.x = (k0 < cnt) ? tile[k0 * 66 + h] : __half(0.0f);
            o.y = (k1 < cnt) ? tile[k1 * 66 + h] : __half(0.0f);
            reinterpret_cast<__half2*>(g_WC + (((size_t)i * NH + h) << 9))[kp] = o;
        }
    }
}

// ---------------- pre-pass 3: sort nets by cnt (descending) ----------------
__global__ __launch_bounds__(512) void rank_kernel() {
    __shared__ int cs[NV];
    const int i = threadIdx.x;
    cs[i] = g_cnt[i];
    __syncthreads();
    const int c = cs[i];
    int r = 0;
    #pragma unroll 8
    for (int j = 0; j < NV; j++) {
        int cj = cs[j];
        r += (cj > c) || (cj == c && j < i);
    }
    g_perm[r] = (uint16_t)i;
}

// ---------------- main GEMM + fused epilogue (R13/R15-proven body) ----------------
__global__ __launch_bounds__(256, 2)
void dag_f16_kernel(const float* __restrict__ b1,
                    const float* __restrict__ W2,
                    const float* __restrict__ b2,
                    float* __restrict__ out)
{
    extern __shared__ char smem[];
    const uint32_t sb = smem_u32(smem);
    const int tid  = threadIdx.x;
    const int warp = tid >> 5;           // 0..7 : 32-row m-slice
    const int lane = tid & 31;
    const int g    = lane >> 2;
    const int t    = lane & 3;

    const int i     = g_perm[blockIdx.y];
    const int bbase = blockIdx.x * BM;

    float* b1s = reinterpret_cast<float*>(smem + SM_PARAMS);          // [64]
    float* w2s = reinterpret_cast<float*>(smem + SM_PARAMS + 256);    // [64]
    float* b2s = reinterpret_cast<float*>(smem + SM_PARAMS + 512);    // [1]
    uint16_t* idxs = reinterpret_cast<uint16_t*>(smem + SM_IDX);      // [512]
    if (tid < 64) {
        b1s[tid] = b1[(size_t)i * NH + tid];
        w2s[tid] = W2[(size_t)i * NH + tid];
        if (tid == 0) b2s[0] = b2[i];
    }
    reinterpret_cast<uint32_t*>(idxs)[tid] =
        reinterpret_cast<const uint32_t*>(g_idx + (size_t)i * NV)[tid];
    const int cnt = g_cnt[i];
    const int ns  = (cnt + 31) >> 5;
    // last stage covers only the low half (k-rows <= 16)? then skip its kk=1
    const int lastkk = (cnt - ((ns - 1) << 5) <= 16) ? 1 : 2;
    __syncthreads();

    float acc[2][8][4];
    #pragma unroll
    for (int mt = 0; mt < 2; mt++)
        #pragma unroll
        for (int nt = 0; nt < 8; nt++)
            #pragma unroll
            for (int q = 0; q < 4; q++) acc[mt][nt][q] = 0.0f;

    auto load_stage = [&](int s) {
        const int buf = s & 3;
        const uint32_t aB = sb + buf * STAGE_B;
        const uint32_t bB = aB + A_BYTES;
        #pragma unroll
        for (int l = 0; l < 4; l++) {         // A: 1024 chunks, gathered rows of XT
            int c = tid + l * 256;
            int krow = c >> 5, mc = c & 31;
            uint32_t xrow = idxs[s * BK + krow];
            cp16(aB + krow * A_PITCH + mc * 16,
                 g_XT + (size_t)xrow * NB + bbase + mc * 8);
        }
        {                                     // B: 256 chunks from compact WC
            int n = tid >> 2, q = tid & 3;    // n = h (0..63)
            cp16(bB + n * B_ROW_B + q * 16,
                 g_WC + (((size_t)i * NH + n) << 9) + s * BK + q * 8);
        }
        cp_commit();
    };

    #pragma unroll
    for (int sp = 0; sp < 3; sp++) {
        if (sp < ns) load_stage(sp); else cp_commit();
    }

    // A-side ldmatrix.x4.trans lane offset (constant across stages)
    const int lr   = lane & 7;
    const int sel  = lane >> 3;
    const int kofs = (sel & 2) ? 8 : 0;
    const int mofs = (sel & 1) ? 8 : 0;
    const uint32_t a_lane_off =
        (uint32_t)((kofs + lr) * A_PITCH + (warp * 32 + mofs) * 2);

    // one k16 halfstage of MMAs (kk constant at each inlined call site)
    auto do_kk = [&](int kk, uint32_t aBl, const char* bBc) {
        uint32_t afr[2][4];
        #pragma unroll
        for (int mt = 0; mt < 2; mt++)
            LDMX4T(afr[mt], aBl + kk * (16 * A_PITCH) + mt * 32);
        uint32_t bfr[8][2];
        #pragma unroll
        for (int nt = 0; nt < 8; nt++) {
            int n = nt * 8 + g;
            const char* p = bBc + (n * 20 + kk * 8 + t) * 4;
            bfr[nt][0] = *reinterpret_cast<const uint32_t*>(p);
            bfr[nt][1] = *reinterpret_cast<const uint32_t*>(p + 16);
        }
        #pragma unroll
        for (int mt = 0; mt < 2; mt++)
            #pragma unroll
            for (int nt = 0; nt < 8; nt++)
                mma_f16(acc[mt][nt], afr[mt], bfr[nt]);
    };

    for (int s = 0; s < ns; s++) {
        asm volatile("cp.async.wait_group 2;" ::: "memory");
        __syncthreads();
        if (s + 3 < ns) load_stage(s + 3); else cp_commit();

        const int buf = s & 3;
        const uint32_t aBl = sb + buf * STAGE_B + a_lane_off;
        const char* bBc = smem + buf * STAGE_B + A_BYTES;

        do_kk(0, aBl, bBc);
        if (s + 1 < ns || lastkk == 2)
            do_kk(1, aBl, bBc);
    }

    // epilogue: recon[row][i] = sum_h relu(acc + b1) * w2 + b2
    #pragma unroll
    for (int mt = 0; mt < 2; mt++) {
        #pragma unroll
        for (int half = 0; half < 2; half++) {
            float sum = 0.0f;
            #pragma unroll
            for (int nt = 0; nt < 8; nt++) {
                int col = nt * 8 + 2 * t;
                float v0 = acc[mt][nt][half * 2 + 0];
                float v1 = acc[mt][nt][half * 2 + 1];
                sum += fmaxf(v0 + b1s[col],     0.0f) * w2s[col];
                sum += fmaxf(v1 + b1s[col + 1], 0.0f) * w2s[col + 1];
            }
            sum += __shfl_xor_sync(0xFFFFFFFFu, sum, 1);
            sum += __shfl_xor_sync(0xFFFFFFFFu, sum, 2);
            if (t == 0) {
                int row = bbase + warp * 32 + mt * 16 + half * 8 + g;
                out[(size_t)row * NV + i] = sum + b2s[0];
            }
        }
    }
}

extern "C" void kernel_launch(void* const* d_in, const int* in_sizes, int n_in,
                              void* d_out, int out_size)
{
    const float* X      = (const float*)d_in[0];
    const float* logits = (const float*)d_in[1];
    const float* W1     = (const float*)d_in[2];
    const float* b1     = (const float*)d_in[3];
    const float* W2     = (const float*)d_in[4];
    const float* b2     = (const float*)d_in[5];
    float* out          = (float*)d_out;

    static bool attr_done = false;
    if (!attr_done) {
        cudaFuncSetAttribute(compact_kernel, cudaFuncAttributeMaxDynamicSharedMemorySize, CW_SMEM);
        cudaFuncSetAttribute(dag_f16_kernel, cudaFuncAttributeMaxDynamicSharedMemorySize, SMEM_MAIN);
        attr_done = true;
    }

    dim3 xtg(NB / 64, NV / 64);           // (64, 8) = 512 blocks
    xt_kernel<<<xtg, 256>>>(X, logits, out);
    compact_kernel<<<NV, 512, CW_SMEM>>>(W1, logits);
    rank_kernel<<<1, NV>>>();

    dim3 grid(NB / BM, NV);               // (16, 512)
    dag_f16_kernel<<<grid, 256, SMEM_MAIN>>>(b1, W2, b2, out);
}